// round 1
// baseline (speedup 1.0000x reference)
#include <cuda_runtime.h>
#include <cstdint>

// Problem constants (fixed by reference setup_inputs)
#define B_   4
#define N_   16384
#define C_   64
#define NQ_  256
#define NS_  32

// Output layout (assumed: tuple outputs flattened + concatenated, float32):
//   grouped_xyz : [B, 3,   NQ, NS]   -> 98304 floats
//   new_features: [B, 3+C, NQ, NS]   -> 2195456 floats
//   mask        : [B, NQ, NS]        -> 32768 floats (all zeros; see analysis)
// total = 2326528

__global__ __launch_bounds__(256) void boxquery_group_kernel(
    const float* __restrict__ xyz,    // [B, N, 3]
    const float* __restrict__ feat,   // [B, C, N]
    const float* __restrict__ qbox,   // [B, NQ, 6]
    float* __restrict__ out)
{
    const int bq = blockIdx.x;          // 0 .. B*NQ-1
    const int b  = bq / NQ_;
    const int q  = bq % NQ_;
    const int tid  = threadIdx.x;
    const int lane = tid & 31;

    __shared__ int   sidx[NS_];
    __shared__ float sgx[3][NS_];

    // Box parameters
    const float* box = qbox + (size_t)(b * NQ_ + q) * 6;
    const float cx = box[0], cy = box[1], cz = box[2];
    const float hx = 0.5f * box[3], hy = 0.5f * box[4], hz = 0.5f * box[5];

    const float* xb = xyz + (size_t)b * N_ * 3;

    // ---- Phase 1 (warp 0): collect first NS_ indices with idx_f == 0 ----
    // idx_f[n] == 0  <=>  (n == 0) || !in_box(n).  Stable ascending argsort
    // puts these first, in ascending n. Ballot-compact over 32-point chunks.
    if (tid < 32) {
        int count = 0;
        int base  = 0;
        while (count < NS_ && base < N_) {
            const int n = base + lane;
            bool acc = false;
            // n < N_ always here since N_ % 32 == 0
            {
                const float px = xb[n * 3 + 0];
                const float py = xb[n * 3 + 1];
                const float pz = xb[n * 3 + 2];
                const bool inb = (fabsf(px - cx) <= hx) &
                                 (fabsf(py - cy) <= hy) &
                                 (fabsf(pz - cz) <= hz);
                acc = (n == 0) || (!inb);
            }
            const unsigned m   = __ballot_sync(0xffffffffu, acc);
            const int      pre = __popc(m & ((1u << lane) - 1u));
            const int      pos = count + pre;
            if (acc && pos < NS_) sidx[pos] = n;
            count += __popc(m);
            base  += 32;
        }
        // ---- Phase 2 (defensive, statistically never taken): if fewer than
        // NS_ zero-entries exist, the argsort tail is in-box indices n>0
        // in ascending order. ----
        if (count < NS_) {
            int base2 = 0;
            while (count < NS_ && base2 < N_) {
                const int n = base2 + lane;
                bool acc = false;
                {
                    const float px = xb[n * 3 + 0];
                    const float py = xb[n * 3 + 1];
                    const float pz = xb[n * 3 + 2];
                    const bool inb = (fabsf(px - cx) <= hx) &
                                     (fabsf(py - cy) <= hy) &
                                     (fabsf(pz - cz) <= hz);
                    acc = (n != 0) && inb;
                }
                const unsigned m   = __ballot_sync(0xffffffffu, acc);
                const int      pre = __popc(m & ((1u << lane) - 1u));
                const int      pos = count + pre;
                if (acc && pos < NS_) sidx[pos] = n;
                count += __popc(m);
                base2 += 32;
            }
        }
        __syncwarp();
        // Gather xyz for selected indices, subtract center
        const int n = sidx[lane];
        sgx[0][lane] = xb[n * 3 + 0] - cx;
        sgx[1][lane] = xb[n * 3 + 1] - cy;
        sgx[2][lane] = xb[n * 3 + 2] - cz;
    }
    __syncthreads();

    // ---- Phase 3: coalesced output writes ----
    float* out_gx = out;                                      // [B,3,NQ,NS]
    float* out_nf = out + (size_t)B_ * 3 * NQ_ * NS_;         // [B,3+C,NQ,NS]
    float* out_mk = out_nf + (size_t)B_ * (3 + C_) * NQ_ * NS_; // [B,NQ,NS]

    // grouped_xyz and the first 3 channels of new_features (identical values)
    if (tid < 3 * NS_) {
        const int d = tid / NS_;
        const int k = tid % NS_;
        const float v = sgx[d][k];
        out_gx[((size_t)(b * 3 + d) * NQ_ + q) * NS_ + k]        = v;
        out_nf[((size_t)(b * (3 + C_) + d) * NQ_ + q) * NS_ + k] = v;
    }
    // mask: all False (index 0 only ever appears at slot 0, which is forced False)
    if (tid >= 3 * NS_ && tid < 4 * NS_) {
        out_mk[(size_t)(b * NQ_ + q) * NS_ + (tid - 3 * NS_)] = 0.0f;
    }

    // feature channels 3..66 of new_features
    const float* fb = feat + (size_t)b * C_ * N_;
    for (int idx = tid; idx < C_ * NS_; idx += 256) {
        const int c = idx / NS_;        // warp handles one channel (k spans lanes)
        const int k = idx % NS_;
        const int n = sidx[k];
        out_nf[((size_t)(b * (3 + C_) + (3 + c)) * NQ_ + q) * NS_ + k] = fb[(size_t)c * N_ + n];
    }
}

extern "C" void kernel_launch(void* const* d_in, const int* in_sizes, int n_in,
                              void* d_out, int out_size)
{
    const float* key_xyz      = (const float*)d_in[0];  // [4,16384,3]
    const float* key_features = (const float*)d_in[1];  // [4,64,16384]
    const float* query_box    = (const float*)d_in[2];  // [4,256,6]
    float* out = (float*)d_out;

    boxquery_group_kernel<<<B_ * NQ_, 256>>>(key_xyz, key_features, query_box, out);
}